// round 6
// baseline (speedup 1.0000x reference)
#include <cuda_runtime.h>

#define NN 524288
#define EE 8388608
#define EV (EE/4)
#define NPG 8192
#define NB 64
#define NWORDS (NN/32)
#define CAP0 (1<<16)
#define CAP1 (1<<20)
#define CAP2 (1<<22)

__device__ __align__(128) float g_deg[NN];
__device__ __align__(128) float g_hs[NN*8];    // dis*h1 (prescaled)
__device__ __align__(128) float g_acc1[NN*8];
__device__ __align__(128) float g_h2s[NN*8];   // dis*h2
__device__ __align__(128) float g_acc2[NN*8];
__device__ __align__(128) float g_h3s[NN];
__device__ __align__(128) float g_acc3[NN];
__device__ unsigned g_bmG[NWORDS];             // growing frontier S1 -> S2
__device__ int g_list0[CAP0];                  // edges into targets
__device__ int g_list1[CAP1];                  // edges into S1
__device__ int g_list2[CAP2];                  // edges into S2
__device__ int g_nl1[1<<16];                   // S1 nodes (targets + grown)
__device__ int g_nl2[1<<20];                   // S2 \ S1 nodes
__device__ int g_cnt0, g_cnt1, g_cnt2, g_cntn1, g_cntn2;

__device__ __forceinline__ void wappend(bool pred, int val, int* cnt, int* list, int cap){
  unsigned m = __ballot_sync(0xffffffffu, pred);
  if (!m) return;
  int lane = threadIdx.x & 31;
  int leader = __ffs(m) - 1;
  int base = 0;
  if (lane == leader) base = atomicAdd(cnt, __popc(m));
  base = __shfl_sync(0xffffffffu, base, leader);
  if (pred){
    int p = base + __popc(m & ((1u<<lane)-1u));
    if (p < cap) list[p] = val;
  }
}

__device__ __forceinline__ void zero8(float* p){
  float4 z = make_float4(0.f,0.f,0.f,0.f);
  ((float4*)p)[0] = z; ((float4*)p)[1] = z;
}

// 1. deg=1 everywhere, clear bitmap + counters
__global__ __launch_bounds__(1024) void k_init(){
  int i = blockIdx.x*1024 + threadIdx.x;
  g_deg[i] = 1.0f;
  if (i < NWORDS) g_bmG[i] = 0u;
  if (i == 0){ g_cnt0=0; g_cnt1=0; g_cnt2=0; g_cntn2=0; g_cntn1=NB; }
}

// 2. mark targets: set bmG bit, seed nl1, zero their accumulators
__global__ void k_mark(const int* __restrict__ tgt){
  int g = threadIdx.x;                 // 64 threads
  int t = g*NPG + tgt[g];
  atomicOr(&g_bmG[t>>5], 1u<<(t&31));
  g_nl1[g] = t;
  zero8(g_acc1 + (size_t)t*8);
  zero8(g_acc2 + (size_t)t*8);
  g_acc3[t] = 0.f;
}

// 3. dense degree + collect edges into targets (arithmetic membership test)
__global__ __launch_bounds__(1024) void k_degscan0(const int4* __restrict__ dst4,
                                                   const int* __restrict__ tgt){
  __shared__ int s_tgt[NB];
  if (threadIdx.x < NB) s_tgt[threadIdx.x] = tgt[threadIdx.x];
  __syncthreads();
  int i = blockIdx.x*1024 + threadIdx.x;      // exactly EV threads
  int4 d = dst4[i];
  atomicAdd(&g_deg[d.x],1.f); atomicAdd(&g_deg[d.y],1.f);
  atomicAdd(&g_deg[d.z],1.f); atomicAdd(&g_deg[d.w],1.f);
  bool p0 = (d.x & (NPG-1)) == s_tgt[d.x>>13];
  bool p1 = (d.y & (NPG-1)) == s_tgt[d.y>>13];
  bool p2 = (d.z & (NPG-1)) == s_tgt[d.z>>13];
  bool p3 = (d.w & (NPG-1)) == s_tgt[d.w>>13];
  if (__ballot_sync(0xffffffffu, p0|p1|p2|p3)){
    int e0 = 4*i;
    wappend(p0, e0,   &g_cnt0, g_list0, CAP0);
    wappend(p1, e0+1, &g_cnt0, g_list0, CAP0);
    wappend(p2, e0+2, &g_cnt0, g_list0, CAP0);
    wappend(p3, e0+3, &g_cnt0, g_list0, CAP0);
  }
}

// 4. dense h1 with prescale: hs = rsqrt(deg) * (x @ W1).  8 threads/node.  [PROFILE SLOT]
__global__ __launch_bounds__(256) void k_h1(const float* __restrict__ x,
                                            const float* __restrict__ W1){
  __shared__ float sW[128*9];
  int t = threadIdx.x;
  for (int i = t; i < 1024; i += 256) sW[(i>>3)*9 + (i&7)] = W1[i];
  __syncthreads();
  int sub  = t & 7;
  int node = blockIdx.x*32 + (t>>3);
  const float* xr = x + (size_t)node*128 + sub*4;
  float acc[8];
  #pragma unroll
  for (int j=0;j<8;j++) acc[j] = 0.f;
  #pragma unroll
  for (int q=0;q<4;q++){
    float4 v = *(const float4*)(xr + 32*q);
    float xt[4] = {v.x, v.y, v.z, v.w};
    #pragma unroll
    for (int u=0;u<4;u++){
      const float* w = &sW[(32*q + 4*sub + u)*9];
      #pragma unroll
      for (int j=0;j<8;j++) acc[j] += xt[u]*w[j];
    }
  }
  #pragma unroll
  for (int off=4; off; off>>=1){
    #pragma unroll
    for (int j=0;j<8;j++) acc[j] += __shfl_xor_sync(0xffffffffu, acc[j], off);
  }
  if (sub == 0){
    float r = rsqrtf(g_deg[node]);
    float* hp = g_hs + (size_t)node*8;
    *(float4*)hp     = make_float4(acc[0]*r,acc[1]*r,acc[2]*r,acc[3]*r);
    *(float4*)(hp+4) = make_float4(acc[4]*r,acc[5]*r,acc[6]*r,acc[7]*r);
  }
}

// 5. grow frontier from list0 srcs: dedup append to nl1, zero acc1/acc2
__global__ __launch_bounds__(1024) void k_srcs0(const int* __restrict__ srcp){
  int n = min(g_cnt0, CAP0);
  for (int i = blockIdx.x*blockDim.x + threadIdx.x; i < n; i += gridDim.x*blockDim.x){
    int s = srcp[g_list0[i]];
    unsigned bit = 1u<<(s&31);
    unsigned old = atomicOr(&g_bmG[s>>5], bit);
    if (!(old & bit)){
      int p = atomicAdd(&g_cntn1, 1);
      g_nl1[p] = s;
      zero8(g_acc1 + (size_t)s*8);
      zero8(g_acc2 + (size_t)s*8);
    }
  }
}

// 6/8. full-E scan: collect edges whose dst bit is set (smem bitmap copy)
__global__ __launch_bounds__(512) void k_scan(const int4* __restrict__ dst4, int which){
  extern __shared__ unsigned sbm[];
  const uint4* bm4 = (const uint4*)g_bmG;
  uint4* s4 = (uint4*)sbm;
  for (int i = threadIdx.x; i < NWORDS/4; i += 512) s4[i] = bm4[i];
  __syncthreads();
  int* cnt  = (which==1) ? &g_cnt1 : &g_cnt2;
  int* list = (which==1) ? g_list1 : g_list2;
  int cap   = (which==1) ? CAP1 : CAP2;
  int stride = gridDim.x*512;
  for (int i = blockIdx.x*512 + threadIdx.x; i < EV; i += stride){
    int4 d = dst4[i];
    bool p0 = (sbm[d.x>>5]>>(d.x&31))&1u;
    bool p1 = (sbm[d.y>>5]>>(d.y&31))&1u;
    bool p2 = (sbm[d.z>>5]>>(d.z&31))&1u;
    bool p3 = (sbm[d.w>>5]>>(d.w&31))&1u;
    if (__ballot_sync(0xffffffffu, p0|p1|p2|p3)){
      int e0 = 4*i;
      wappend(p0, e0,   cnt, list, cap);
      wappend(p1, e0+1, cnt, list, cap);
      wappend(p2, e0+2, cnt, list, cap);
      wappend(p3, e0+3, cnt, list, cap);
    }
  }
}

// 7. grow frontier from list1 srcs: dedup append to nl2, zero acc1
__global__ __launch_bounds__(512) void k_srcs1(const int* __restrict__ srcp){
  int n = min(g_cnt1, CAP1);
  for (int i = blockIdx.x*blockDim.x + threadIdx.x; i < n; i += gridDim.x*blockDim.x){
    int s = srcp[g_list1[i]];
    unsigned bit = 1u<<(s&31);
    unsigned old = atomicOr(&g_bmG[s>>5], bit);
    if (!(old & bit)){
      int p = atomicAdd(&g_cntn2, 1);
      g_nl2[p] = s;
      zero8(g_acc1 + (size_t)s*8);
    }
  }
}

// 9. sparse layer-1 aggregation over edges into S2
__global__ __launch_bounds__(256) void k_agg1s(const int* __restrict__ srcp, const int* __restrict__ dstp){
  int n = min(g_cnt2, CAP2);
  for (int i = blockIdx.x*blockDim.x + threadIdx.x; i < n; i += gridDim.x*blockDim.x){
    int e = g_list2[i];
    int s = srcp[e], d = dstp[e];
    const float* hp = g_hs + (size_t)s*8;
    float4 a = *(const float4*)hp, b = *(const float4*)(hp+4);
    float* ap = g_acc1 + (size_t)d*8;
    atomicAdd((float4*)ap, a);
    atomicAdd((float4*)(ap+4), b);
  }
}

// 10. fused tail (single block): h2 -> agg2 -> h3 -> agg3 -> head
__global__ __launch_bounds__(1024) void k_tail(const int* __restrict__ srcp, const int* __restrict__ dstp,
                       const float* __restrict__ W2, const float* __restrict__ b1,
                       const float* __restrict__ W3, const float* __restrict__ b2,
                       const float* __restrict__ b3,
                       const float* __restrict__ Wl1, const float* __restrict__ bl1,
                       const float* __restrict__ Wl2, const float* __restrict__ bl2,
                       float* __restrict__ out){
  __shared__ float sW2[64], sb1[8], sW3[8], sb2[8];
  __shared__ float sWl1[17*16], sbl1[16], sWl2[32], sbl2[2];
  int t = threadIdx.x;
  if (t < 64) sW2[t] = W2[t];
  if (t < 8){ sb1[t] = b1[t]; sW3[t] = W3[t]; sb2[t] = b2[t]; }
  for (int i = t; i < 17*16; i += 1024) sWl1[i] = Wl1[i];
  if (t < 16) sbl1[t] = bl1[t];
  if (t < 32) sWl2[t] = Wl2[t];
  if (t < 2)  sbl2[t] = bl2[t];
  __syncthreads();

  // phase A: x1 = relu(r*(acc1+hs)+b1); h2s = r*(x1@W2) over S2 = nl1 ++ nl2
  int n1 = g_cntn1, n2 = g_cntn2;
  int nS2 = n1 + n2;
  for (int i = t; i < nS2; i += 1024){
    int node = (i < n1) ? g_nl1[i] : g_nl2[i - n1];
    float r = rsqrtf(g_deg[node]);
    const float* ap = g_acc1 + (size_t)node*8;
    const float* hp = g_hs  + (size_t)node*8;
    float x1[8];
    #pragma unroll
    for (int j=0;j<8;j++) x1[j] = fmaxf(r*(ap[j]+hp[j]) + sb1[j], 0.f);
    float* h2p = g_h2s + (size_t)node*8;
    #pragma unroll
    for (int j=0;j<8;j++){
      float s2 = 0.f;
      #pragma unroll
      for (int u=0;u<8;u++) s2 += x1[u]*sW2[u*8+j];
      h2p[j] = r*s2;
    }
  }
  __syncthreads();

  // phase B: acc2[d] += h2s[s] over list1
  int m1 = min(g_cnt1, CAP1);
  for (int i = t; i < m1; i += 1024){
    int e = g_list1[i];
    int s = srcp[e], d = dstp[e];
    const float* hp = g_h2s + (size_t)s*8;
    float4 a = *(const float4*)hp, b = *(const float4*)(hp+4);
    float* ap = g_acc2 + (size_t)d*8;
    atomicAdd((float4*)ap, a);
    atomicAdd((float4*)(ap+4), b);
  }
  __syncthreads();

  // phase C: h3s = r*(relu(r*(acc2+h2s)+b2) . W3) over S1 (nl1)
  for (int i = t; i < n1; i += 1024){
    int node = g_nl1[i];
    float r = rsqrtf(g_deg[node]);
    const float* ap = g_acc2 + (size_t)node*8;
    const float* hp = g_h2s + (size_t)node*8;
    float s2 = 0.f;
    #pragma unroll
    for (int j=0;j<8;j++) s2 += fmaxf(r*(ap[j]+hp[j]) + sb2[j], 0.f)*sW3[j];
    g_h3s[node] = r*s2;
  }
  __syncthreads();

  // phase D: acc3[d] += h3s[s] over list0
  int m0 = min(g_cnt0, CAP0);
  for (int i = t; i < m0; i += 1024){
    int e = g_list0[i];
    atomicAdd(&g_acc3[dstp[e]], g_h3s[srcp[e]]);
  }
  __syncthreads();

  // phase E: head MLP at targets (first 64 nl1 entries are the targets, in order)
  if (t < NB){
    int node = g_nl1[t];
    float r = rsqrtf(g_deg[node]);
    float f[17];
    const float* a1 = g_acc1 + (size_t)node*8;
    const float* h1 = g_hs  + (size_t)node*8;
    const float* a2 = g_acc2 + (size_t)node*8;
    const float* h2 = g_h2s + (size_t)node*8;
    #pragma unroll
    for (int j=0;j<8;j++) f[j]   = fmaxf(r*(a1[j]+h1[j]) + sb1[j], 0.f);
    #pragma unroll
    for (int j=0;j<8;j++) f[8+j] = fmaxf(r*(a2[j]+h2[j]) + sb2[j], 0.f);
    f[16] = fmaxf(r*(g_acc3[node]+g_h3s[node]) + b3[0], 0.f);
    float z[16];
    #pragma unroll
    for (int j=0;j<16;j++){
      float s2 = sbl1[j];
      #pragma unroll
      for (int u=0;u<17;u++) s2 += f[u]*sWl1[u*16+j];
      z[j] = fmaxf(s2, 0.f);
    }
    #pragma unroll
    for (int o=0;o<2;o++){
      float s2 = sbl2[o];
      #pragma unroll
      for (int u=0;u<16;u++) s2 += z[u]*sWl2[u*2+o];
      out[t*2+o] = s2;
    }
  }
}

extern "C" void kernel_launch(void* const* d_in, const int* in_sizes, int n_in,
                              void* d_out, int out_size){
  const float* x    = (const float*)d_in[0];
  const int*   ei   = (const int*)  d_in[1];
  const int*   tgt  = (const int*)  d_in[2];
  const float* W1   = (const float*)d_in[3];
  const float* b1   = (const float*)d_in[4];
  const float* W2   = (const float*)d_in[5];
  const float* b2   = (const float*)d_in[6];
  const float* W3   = (const float*)d_in[7];
  const float* b3   = (const float*)d_in[8];
  const float* Wl1  = (const float*)d_in[9];
  const float* bl1  = (const float*)d_in[10];
  const float* Wl2  = (const float*)d_in[11];
  const float* bl2  = (const float*)d_in[12];
  const int* srcp = ei;
  const int* dstp = ei + EE;
  const int4* dst4 = (const int4*)dstp;
  float* out = (float*)d_out;

  cudaFuncSetAttribute(k_scan, cudaFuncAttributeMaxDynamicSharedMemorySize, NWORDS*4);

  k_init<<<NN/1024, 1024>>>();                       // 1
  k_mark<<<1, 64>>>(tgt);                            // 2
  k_degscan0<<<EV/1024, 1024>>>(dst4, tgt);          // 3: deg + list0
  k_h1<<<NN/32, 256>>>(x, W1);                       // 4: PROFILED
  k_srcs0<<<4, 1024>>>(srcp);                        // 5: bmG = S1, nl1
  k_scan<<<444, 512, NWORDS*4>>>(dst4, 1);           // 6: list1 = edges into S1
  k_srcs1<<<32, 512>>>(srcp);                        // 7: bmG = S2, nl2
  k_scan<<<444, 512, NWORDS*4>>>(dst4, 2);           // 8: list2 = edges into S2
  k_agg1s<<<512, 256>>>(srcp, dstp);                 // 9
  k_tail<<<1, 1024>>>(srcp, dstp, W2, b1, W3, b2, b3, Wl1, bl1, Wl2, bl2, out); // 10
}

// round 8
// speedup vs baseline: 1.0171x; 1.0171x over previous
#include <cuda_runtime.h>

#define NN 524288
#define EE 8388608
#define EV (EE/4)
#define NPG 8192
#define NB 64
#define NWORDS (NN/32)
#define CAP0 (1<<16)
#define CAP1 (1<<19)
#define CAP2 (1<<22)

__device__ __align__(128) float g_deg[NN];
__device__ __align__(128) float g_hs[NN*8];    // dis*h1 (prescaled)
__device__ __align__(128) float g_acc1[NN*8];
__device__ __align__(128) float g_h2s[NN*8];   // dis*h2
__device__ __align__(128) float g_acc2[NN*8];
__device__ __align__(128) float g_h3s[NN];
__device__ __align__(128) float g_acc3[NN];
__device__ unsigned g_bmG[NWORDS];             // growing frontier S1 -> S2 -> S3
__device__ int2 g_list0[CAP0];                 // (src,dst) of edges into targets
__device__ int2 g_list1[CAP1];                 // (e,dst) -> rewritten (src,dst), edges into S1
__device__ int2 g_list2[CAP2];                 // (e,dst) -> rewritten (src,dst), edges into S2
__device__ int g_nl1[1<<16];                   // S1 nodes (targets first)
__device__ int g_nl2[1<<20];                   // S2 \ S1
__device__ int g_nl3[NN];                      // S3 \ S2
__device__ int g_cnt0, g_cnt1, g_cnt2, g_n1, g_n2, g_n3;

__device__ __forceinline__ void zero8(float* p){
  float4 z = make_float4(0.f,0.f,0.f,0.f);
  ((float4*)p)[0] = z; ((float4*)p)[1] = z;
}

__device__ __forceinline__ void wappend2(bool pred, int2 val, int* cnt, int2* list, int cap){
  unsigned m = __ballot_sync(0xffffffffu, pred);
  if (!m) return;
  int lane = threadIdx.x & 31;
  int leader = __ffs(m) - 1;
  int base = 0;
  if (lane == leader) base = atomicAdd(cnt, __popc(m));
  base = __shfl_sync(0xffffffffu, base, leader);
  if (pred){
    int p = base + __popc(m & ((1u<<lane)-1u));
    if (p < cap) list[p] = val;
  }
}

// 1. deg=1, clear bitmap, counters
__global__ __launch_bounds__(1024) void k_init(){
  int i = blockIdx.x*1024 + threadIdx.x;
  g_deg[i] = 1.0f;
  if (i < NWORDS) g_bmG[i] = 0u;
  if (i == 0){ g_cnt0=0; g_cnt1=0; g_cnt2=0; g_n1=NB; g_n2=0; g_n3=0; }
}

// 2. mark targets
__global__ void k_mark(const int* __restrict__ tgt){
  int g = threadIdx.x;  // 64
  int t = g*NPG + tgt[g];
  atomicOr(&g_bmG[t>>5], 1u<<(t&31));
  g_nl1[g] = t;
  zero8(g_acc1 + (size_t)t*8);
  zero8(g_acc2 + (size_t)t*8);
  g_acc3[t] = 0.f;
}

// 3. scan0 (arithmetic target test, safe to grow bmG inline) + build S1
__global__ __launch_bounds__(1024) void k_scan0s(const int4* __restrict__ dst4,
                                                 const int* __restrict__ srcp,
                                                 const int* __restrict__ tgt){
  __shared__ int s_tgt[NB];
  if (threadIdx.x < NB) s_tgt[threadIdx.x] = tgt[threadIdx.x];
  __syncthreads();
  int i = blockIdx.x*1024 + threadIdx.x;     // exactly EV
  int4 d = dst4[i];
  bool p0 = (d.x & (NPG-1)) == s_tgt[d.x>>13];
  bool p1 = (d.y & (NPG-1)) == s_tgt[d.y>>13];
  bool p2 = (d.z & (NPG-1)) == s_tgt[d.z>>13];
  bool p3 = (d.w & (NPG-1)) == s_tgt[d.w>>13];
  if (!__ballot_sync(0xffffffffu, p0|p1|p2|p3)) return;
  int e0 = 4*i;
  int s0=0,s1=0,s2=0,s3=0;
  if (p0) s0 = srcp[e0];
  if (p1) s1 = srcp[e0+1];
  if (p2) s2 = srcp[e0+2];
  if (p3) s3 = srcp[e0+3];
  wappend2(p0, make_int2(s0,d.x), &g_cnt0, g_list0, CAP0);
  wappend2(p1, make_int2(s1,d.y), &g_cnt0, g_list0, CAP0);
  wappend2(p2, make_int2(s2,d.z), &g_cnt0, g_list0, CAP0);
  wappend2(p3, make_int2(s3,d.w), &g_cnt0, g_list0, CAP0);
  #pragma unroll
  for (int u=0;u<4;u++){
    bool p = (u==0)?p0:(u==1)?p1:(u==2)?p2:p3;
    int  s = (u==0)?s0:(u==1)?s1:(u==2)?s2:s3;
    if (p){
      unsigned bit = 1u<<(s&31);
      unsigned old = atomicOr(&g_bmG[s>>5], bit);
      if (!(old & bit)){
        int p2i = atomicAdd(&g_n1, 1);
        g_nl1[p2i] = s;
        zero8(g_acc1 + (size_t)s*8);
        zero8(g_acc2 + (size_t)s*8);
      }
    }
  }
}

// 4. scan1: edges with dst in S1 (frozen bitmap, smem copy)   [PROFILE SLOT]
__global__ __launch_bounds__(512) void k_scan1(const int4* __restrict__ dst4){
  extern __shared__ unsigned sbm[];
  uint4* s4 = (uint4*)sbm;
  const uint4* bm4 = (const uint4*)g_bmG;
  for (int i = threadIdx.x; i < NWORDS/4; i += 512) s4[i] = bm4[i];
  __syncthreads();
  int stride = gridDim.x*512;
  for (int i = blockIdx.x*512 + threadIdx.x; i < EV; i += stride){
    int4 d = dst4[i];
    bool p0 = (sbm[d.x>>5]>>(d.x&31))&1u;
    bool p1 = (sbm[d.y>>5]>>(d.y&31))&1u;
    bool p2 = (sbm[d.z>>5]>>(d.z&31))&1u;
    bool p3 = (sbm[d.w>>5]>>(d.w&31))&1u;
    if (__ballot_sync(0xffffffffu, p0|p1|p2|p3)){
      int e0 = 4*i;
      wappend2(p0, make_int2(e0  ,d.x), &g_cnt1, g_list1, CAP1);
      wappend2(p1, make_int2(e0+1,d.y), &g_cnt1, g_list1, CAP1);
      wappend2(p2, make_int2(e0+2,d.z), &g_cnt1, g_list1, CAP1);
      wappend2(p3, make_int2(e0+3,d.w), &g_cnt1, g_list1, CAP1);
    }
  }
}

// 5. grow S1->S2 from list1 srcs; rewrite list1.x = src
__global__ __launch_bounds__(512) void k_srcs1(const int* __restrict__ srcp){
  int n = min(g_cnt1, CAP1);
  for (int i = blockIdx.x*blockDim.x + threadIdx.x; i < n; i += gridDim.x*blockDim.x){
    int s = srcp[g_list1[i].x];
    g_list1[i].x = s;
    unsigned bit = 1u<<(s&31);
    unsigned old = atomicOr(&g_bmG[s>>5], bit);
    if (!(old & bit)){
      int p = atomicAdd(&g_n2, 1);
      g_nl2[p] = s;
      zero8(g_acc1 + (size_t)s*8);
    }
  }
}

// 6. scan2 + dense degree fused
__global__ __launch_bounds__(512) void k_scan2deg(const int4* __restrict__ dst4){
  extern __shared__ unsigned sbm[];
  uint4* s4 = (uint4*)sbm;
  const uint4* bm4 = (const uint4*)g_bmG;
  for (int i = threadIdx.x; i < NWORDS/4; i += 512) s4[i] = bm4[i];
  __syncthreads();
  int stride = gridDim.x*512;
  for (int i = blockIdx.x*512 + threadIdx.x; i < EV; i += stride){
    int4 d = dst4[i];
    atomicAdd(&g_deg[d.x],1.f); atomicAdd(&g_deg[d.y],1.f);
    atomicAdd(&g_deg[d.z],1.f); atomicAdd(&g_deg[d.w],1.f);
    bool p0 = (sbm[d.x>>5]>>(d.x&31))&1u;
    bool p1 = (sbm[d.y>>5]>>(d.y&31))&1u;
    bool p2 = (sbm[d.z>>5]>>(d.z&31))&1u;
    bool p3 = (sbm[d.w>>5]>>(d.w&31))&1u;
    if (__ballot_sync(0xffffffffu, p0|p1|p2|p3)){
      int e0 = 4*i;
      wappend2(p0, make_int2(e0  ,d.x), &g_cnt2, g_list2, CAP2);
      wappend2(p1, make_int2(e0+1,d.y), &g_cnt2, g_list2, CAP2);
      wappend2(p2, make_int2(e0+2,d.z), &g_cnt2, g_list2, CAP2);
      wappend2(p3, make_int2(e0+3,d.w), &g_cnt2, g_list2, CAP2);
    }
  }
}

// 7. grow S2->S3 from list2 srcs; rewrite list2.x = src (no acc zero needed)
__global__ __launch_bounds__(512) void k_srcs2(const int* __restrict__ srcp){
  int n = min(g_cnt2, CAP2);
  for (int i = blockIdx.x*blockDim.x + threadIdx.x; i < n; i += gridDim.x*blockDim.x){
    int s = srcp[g_list2[i].x];
    g_list2[i].x = s;
    unsigned bit = 1u<<(s&31);
    unsigned old = atomicOr(&g_bmG[s>>5], bit);
    if (!(old & bit)){
      int p = atomicAdd(&g_n3, 1);
      g_nl3[p] = s;
    }
  }
}

// 8. sparse h1 over S3 = nl1 ++ nl2 ++ nl3: hs = rsqrt(deg)*(x@W1). 8 thr/node, float4 weights.
__global__ __launch_bounds__(256) void k_h1s(const float* __restrict__ x,
                                             const float* __restrict__ W1){
  __shared__ float sWT[8*132];   // [j][k], pad 132
  int t = threadIdx.x;
  for (int i = t; i < 1024; i += 256) sWT[(i&7)*132 + (i>>3)] = W1[i];
  __syncthreads();
  int n1 = g_n1, n2 = g_n2, n3 = g_n3;
  int ntot = n1 + n2 + n3;
  int sub  = t & 7;
  int slot = (blockIdx.x*256 + t) >> 3;
  int nslots = (gridDim.x*256) >> 3;
  for (int i = slot; i < ntot; i += nslots){
    int node = (i < n1) ? g_nl1[i] : (i < n1+n2) ? g_nl2[i-n1] : g_nl3[i-n1-n2];
    const float* xr = x + (size_t)node*128 + sub*4;
    float acc[8];
    #pragma unroll
    for (int j=0;j<8;j++) acc[j] = 0.f;
    #pragma unroll
    for (int q=0;q<4;q++){
      float4 xv = *(const float4*)(xr + 32*q);
      int kb = 32*q + 4*sub;
      #pragma unroll
      for (int j=0;j<8;j++){
        float4 wv = *(const float4*)&sWT[j*132 + kb];
        acc[j] += xv.x*wv.x + xv.y*wv.y + xv.z*wv.z + xv.w*wv.w;
      }
    }
    #pragma unroll
    for (int off=4; off; off>>=1){
      #pragma unroll
      for (int j=0;j<8;j++) acc[j] += __shfl_xor_sync(0xffffffffu, acc[j], off);
    }
    if (sub == 0){
      float r = rsqrtf(g_deg[node]);
      float* hp = g_hs + (size_t)node*8;
      *(float4*)hp     = make_float4(acc[0]*r,acc[1]*r,acc[2]*r,acc[3]*r);
      *(float4*)(hp+4) = make_float4(acc[4]*r,acc[5]*r,acc[6]*r,acc[7]*r);
    }
  }
}

// 9. layer-1 aggregation over (src,dst) pairs of edges into S2
__global__ __launch_bounds__(256) void k_agg1s(){
  int n = min(g_cnt2, CAP2);
  for (int i = blockIdx.x*blockDim.x + threadIdx.x; i < n; i += gridDim.x*blockDim.x){
    int2 sd = g_list2[i];
    const float* hp = g_hs + (size_t)sd.x*8;
    float4 a = *(const float4*)hp, b = *(const float4*)(hp+4);
    float* ap = g_acc1 + (size_t)sd.y*8;
    atomicAdd((float4*)ap, a);
    atomicAdd((float4*)(ap+4), b);
  }
}

// 10. fused tail: h2 -> agg2 -> h3 -> agg3 -> head (single block)
__global__ __launch_bounds__(1024) void k_tail(
                       const float* __restrict__ W2, const float* __restrict__ b1,
                       const float* __restrict__ W3, const float* __restrict__ b2,
                       const float* __restrict__ b3,
                       const float* __restrict__ Wl1, const float* __restrict__ bl1,
                       const float* __restrict__ Wl2, const float* __restrict__ bl2,
                       float* __restrict__ out){
  __shared__ float sW2[64], sb1[8], sW3[8], sb2[8];
  __shared__ float sWl1[17*16], sbl1[16], sWl2[32], sbl2[2];
  int t = threadIdx.x;
  if (t < 64) sW2[t] = W2[t];
  if (t < 8){ sb1[t] = b1[t]; sW3[t] = W3[t]; sb2[t] = b2[t]; }
  for (int i = t; i < 17*16; i += 1024) sWl1[i] = Wl1[i];
  if (t < 16) sbl1[t] = bl1[t];
  if (t < 32) sWl2[t] = Wl2[t];
  if (t < 2)  sbl2[t] = bl2[t];
  __syncthreads();

  int n1 = g_n1, n2 = g_n2;
  int nS2 = n1 + n2;
  for (int i = t; i < nS2; i += 1024){
    int node = (i < n1) ? g_nl1[i] : g_nl2[i - n1];
    float r = rsqrtf(g_deg[node]);
    const float* ap = g_acc1 + (size_t)node*8;
    const float* hp = g_hs  + (size_t)node*8;
    float x1[8];
    #pragma unroll
    for (int j=0;j<8;j++) x1[j] = fmaxf(r*(ap[j]+hp[j]) + sb1[j], 0.f);
    float* h2p = g_h2s + (size_t)node*8;
    #pragma unroll
    for (int j=0;j<8;j++){
      float s2 = 0.f;
      #pragma unroll
      for (int u=0;u<8;u++) s2 += x1[u]*sW2[u*8+j];
      h2p[j] = r*s2;
    }
  }
  __syncthreads();

  int m1 = min(g_cnt1, CAP1);
  for (int i = t; i < m1; i += 1024){
    int2 sd = g_list1[i];
    const float* hp = g_h2s + (size_t)sd.x*8;
    float4 a = *(const float4*)hp, b = *(const float4*)(hp+4);
    float* ap = g_acc2 + (size_t)sd.y*8;
    atomicAdd((float4*)ap, a);
    atomicAdd((float4*)(ap+4), b);
  }
  __syncthreads();

  for (int i = t; i < n1; i += 1024){
    int node = g_nl1[i];
    float r = rsqrtf(g_deg[node]);
    const float* ap = g_acc2 + (size_t)node*8;
    const float* hp = g_h2s + (size_t)node*8;
    float s2 = 0.f;
    #pragma unroll
    for (int j=0;j<8;j++) s2 += fmaxf(r*(ap[j]+hp[j]) + sb2[j], 0.f)*sW3[j];
    g_h3s[node] = r*s2;
  }
  __syncthreads();

  int m0 = min(g_cnt0, CAP0);
  for (int i = t; i < m0; i += 1024){
    int2 sd = g_list0[i];
    atomicAdd(&g_acc3[sd.y], g_h3s[sd.x]);
  }
  __syncthreads();

  if (t < NB){
    int node = g_nl1[t];                 // targets are first 64, in order
    float r = rsqrtf(g_deg[node]);
    float f[17];
    const float* a1 = g_acc1 + (size_t)node*8;
    const float* h1 = g_hs  + (size_t)node*8;
    const float* a2 = g_acc2 + (size_t)node*8;
    const float* h2 = g_h2s + (size_t)node*8;
    #pragma unroll
    for (int j=0;j<8;j++) f[j]   = fmaxf(r*(a1[j]+h1[j]) + sb1[j], 0.f);
    #pragma unroll
    for (int j=0;j<8;j++) f[8+j] = fmaxf(r*(a2[j]+h2[j]) + sb2[j], 0.f);
    f[16] = fmaxf(r*(g_acc3[node]+g_h3s[node]) + b3[0], 0.f);
    float z[16];
    #pragma unroll
    for (int j=0;j<16;j++){
      float s2 = sbl1[j];
      #pragma unroll
      for (int u=0;u<17;u++) s2 += f[u]*sWl1[u*16+j];
      z[j] = fmaxf(s2, 0.f);
    }
    #pragma unroll
    for (int o=0;o<2;o++){
      float s2 = sbl2[o];
      #pragma unroll
      for (int u=0;u<16;u++) s2 += z[u]*sWl2[u*2+o];
      out[t*2+o] = s2;
    }
  }
}

extern "C" void kernel_launch(void* const* d_in, const int* in_sizes, int n_in,
                              void* d_out, int out_size){
  const float* x    = (const float*)d_in[0];
  const int*   ei   = (const int*)  d_in[1];
  const int*   tgt  = (const int*)  d_in[2];
  const float* W1   = (const float*)d_in[3];
  const float* b1   = (const float*)d_in[4];
  const float* W2   = (const float*)d_in[5];
  const float* b2   = (const float*)d_in[6];
  const float* W3   = (const float*)d_in[7];
  const float* b3   = (const float*)d_in[8];
  const float* Wl1  = (const float*)d_in[9];
  const float* bl1  = (const float*)d_in[10];
  const float* Wl2  = (const float*)d_in[11];
  const float* bl2  = (const float*)d_in[12];
  const int* srcp = ei;
  const int* dstp = ei + EE;
  const int4* dst4 = (const int4*)dstp;
  float* out = (float*)d_out;

  cudaFuncSetAttribute(k_scan1,    cudaFuncAttributeMaxDynamicSharedMemorySize, NWORDS*4);
  cudaFuncSetAttribute(k_scan2deg, cudaFuncAttributeMaxDynamicSharedMemorySize, NWORDS*4);

  k_init<<<NN/1024, 1024>>>();                          // 1
  k_mark<<<1, 64>>>(tgt);                               // 2
  k_scan0s<<<EV/1024, 1024>>>(dst4, srcp, tgt);         // 3: list0 + S1
  k_scan1<<<444, 512, NWORDS*4>>>(dst4);                // 4: PROFILED
  k_srcs1<<<32, 512>>>(srcp);                           // 5: S2, list1 -> (s,d)
  k_scan2deg<<<444, 512, NWORDS*4>>>(dst4);             // 6: list2 + degree
  k_srcs2<<<256, 512>>>(srcp);                          // 7: S3, list2 -> (s,d)
  k_h1s<<<2048, 256>>>(x, W1);                          // 8: sparse h1
  k_agg1s<<<512, 256>>>();                              // 9
  k_tail<<<1, 1024>>>(W2, b1, W3, b2, b3, Wl1, bl1, Wl2, bl2, out); // 10
}

// round 9
// speedup vs baseline: 1.2257x; 1.2050x over previous
#include <cuda_runtime.h>

#define NN 524288
#define EE 8388608
#define EV (EE/4)
#define NPG 8192
#define NB 64
#define NWORDS (NN/32)
#define CAP0 (1<<16)
#define CAP1 (1<<20)
#define CAP2 (1<<22)
#define NBLK 148
#define NTHR 1024
#define NT (NBLK*NTHR)

__device__ __align__(128) float g_deg[NN];
__device__ __align__(128) float g_hs[NN*8];
__device__ __align__(128) float g_acc1[NN*8];
__device__ __align__(128) float g_h2s[NN*8];
__device__ __align__(128) float g_acc2[NN*8];
__device__ __align__(128) float g_h3s[NN];
__device__ __align__(128) float g_acc3[NN];
__device__ unsigned g_bmG[NWORDS];
__device__ int2 g_list0[CAP0];
__device__ int2 g_list1[CAP1];
__device__ int2 g_list2[CAP2];
__device__ int g_nl1[1<<17];
__device__ int g_nl2[1<<20];
__device__ int g_nl3[NN];
__device__ int g_tn[NB];
__device__ int g_cnt0, g_cnt1, g_cnt2, g_n1, g_n2, g_n3;
__device__ int g_bar_cnt = 0;
__device__ int g_bar_gen = 0;

__device__ __forceinline__ void zero8(float* p){
  float4 z = make_float4(0.f,0.f,0.f,0.f);
  ((float4*)p)[0] = z; ((float4*)p)[1] = z;
}

// grid barrier: 148 blocks, all resident (1 block/SM). generation-based.
__device__ __forceinline__ void gbar(){
  __syncthreads();
  if (threadIdx.x == 0){
    __threadfence();
    int gen = *((volatile int*)&g_bar_gen);
    if (atomicAdd(&g_bar_cnt, 1) == NBLK-1){
      g_bar_cnt = 0;
      __threadfence();
      *((volatile int*)&g_bar_gen) = gen + 1;
    } else {
      while (*((volatile int*)&g_bar_gen) == gen) { }
    }
    __threadfence();
  }
  __syncthreads();
}

__device__ __forceinline__ void wappend2(bool pred, int2 val, int* cnt, int2* list, int cap){
  unsigned m = __ballot_sync(0xffffffffu, pred);
  if (!m) return;
  int lane = threadIdx.x & 31;
  int leader = __ffs(m) - 1;
  int base = 0;
  if (lane == leader) base = atomicAdd(cnt, __popc(m));
  base = __shfl_sync(0xffffffffu, base, leader);
  if (pred){
    int p = base + __popc(m & ((1u<<lane)-1u));
    if (p < cap) list[p] = val;
  }
}

// frontier growth with dedup; optionally zero accumulators of new node
__device__ __forceinline__ void grow(int s, int* nl, int* n, int z1, int z2){
  unsigned bit = 1u<<(s&31);
  unsigned old = atomicOr(&g_bmG[s>>5], bit);
  if (!(old & bit)){
    int p = atomicAdd(n, 1);
    nl[p] = s;
    if (z1) zero8(g_acc1 + (size_t)s*8);
    if (z2) zero8(g_acc2 + (size_t)s*8);
  }
}

__global__ __launch_bounds__(NTHR) void k_mega(
    const float* __restrict__ x, const int* __restrict__ srcp, const int4* __restrict__ dst4,
    const int* __restrict__ tgt,
    const float* __restrict__ W1, const float* __restrict__ b1,
    const float* __restrict__ W2, const float* __restrict__ b2,
    const float* __restrict__ W3, const float* __restrict__ b3,
    const float* __restrict__ Wl1, const float* __restrict__ bl1,
    const float* __restrict__ Wl2, const float* __restrict__ bl2,
    float* __restrict__ out){
  extern __shared__ unsigned sbm[];            // 64 KB bitmap copy
  __shared__ float sWT[8*132];                 // W1 transposed [j][k]
  __shared__ int   s_tgt[NB];
  __shared__ float sW2[64], sb1[8], sW3[8], sb2[8];
  __shared__ float sWl1[17*16], sbl1[16], sWl2[32], sbl2[2];

  int t = threadIdx.x;
  int gtid = blockIdx.x*NTHR + t;

  // load small weights
  if (t < 1024) sWT[(t&7)*132 + (t>>3)] = W1[t];
  if (t < NB) s_tgt[t] = tgt[t];
  if (t < 64) sW2[t] = W2[t];
  if (t < 8){ sb1[t] = b1[t]; sW3[t] = W3[t]; sb2[t] = b2[t]; }
  if (t >= 64 && t < 64+272) sWl1[t-64] = Wl1[t-64];
  if (t >= 384 && t < 400) sbl1[t-384] = bl1[t-384];
  if (t >= 400 && t < 432) sWl2[t-400] = Wl2[t-400];
  if (t >= 432 && t < 434) sbl2[t-432] = bl2[t-432];
  __syncthreads();

  // ---- P0: init ----
  for (int i = gtid; i < NN; i += NT) g_deg[i] = 1.0f;
  for (int i = gtid; i < NWORDS; i += NT) g_bmG[i] = 0u;
  if (gtid == 0){ g_cnt0=0; g_cnt1=0; g_cnt2=0; g_n1=0; g_n2=0; g_n3=0; }
  gbar();

  // ---- P1: mark targets + scan0 (arithmetic test) + dense degree + grow S1 ----
  if (blockIdx.x == 0 && t < NB){
    int node = t*NPG + s_tgt[t];
    g_tn[t] = node;
    unsigned bit = 1u<<(node&31);
    unsigned old = atomicOr(&g_bmG[node>>5], bit);
    if (!(old & bit)){
      int p = atomicAdd(&g_n1, 1);
      g_nl1[p] = node;
      zero8(g_acc1 + (size_t)node*8);
      zero8(g_acc2 + (size_t)node*8);
    }
    g_acc3[node] = 0.f;
  }
  for (int i = gtid; i < EV; i += NT){
    int4 d = dst4[i];
    atomicAdd(&g_deg[d.x],1.f); atomicAdd(&g_deg[d.y],1.f);
    atomicAdd(&g_deg[d.z],1.f); atomicAdd(&g_deg[d.w],1.f);
    bool p0 = (d.x & (NPG-1)) == s_tgt[d.x>>13];
    bool p1 = (d.y & (NPG-1)) == s_tgt[d.y>>13];
    bool p2 = (d.z & (NPG-1)) == s_tgt[d.z>>13];
    bool p3 = (d.w & (NPG-1)) == s_tgt[d.w>>13];
    if (__ballot_sync(0xffffffffu, p0|p1|p2|p3)){
      int e0 = 4*i;
      int s0=0,s1=0,s2=0,s3=0;
      if (p0) s0 = srcp[e0];
      if (p1) s1 = srcp[e0+1];
      if (p2) s2 = srcp[e0+2];
      if (p3) s3 = srcp[e0+3];
      wappend2(p0, make_int2(s0,d.x), &g_cnt0, g_list0, CAP0);
      wappend2(p1, make_int2(s1,d.y), &g_cnt0, g_list0, CAP0);
      wappend2(p2, make_int2(s2,d.z), &g_cnt0, g_list0, CAP0);
      wappend2(p3, make_int2(s3,d.w), &g_cnt0, g_list0, CAP0);
      if (p0) grow(s0, g_nl1, &g_n1, 1, 1);
      if (p1) grow(s1, g_nl1, &g_n1, 1, 1);
      if (p2) grow(s2, g_nl1, &g_n1, 1, 1);
      if (p3) grow(s3, g_nl1, &g_n1, 1, 1);
    }
  }
  gbar();

  // ---- P2: scan1 (smem snapshot of S1) + grow S2 ----
  {
    uint4* s4 = (uint4*)sbm;
    const uint4* bm4 = (const uint4*)g_bmG;
    for (int i = t; i < NWORDS/4; i += NTHR) s4[i] = bm4[i];
    __syncthreads();
    for (int i = gtid; i < EV; i += NT){
      int4 d = dst4[i];
      bool p0 = (sbm[d.x>>5]>>(d.x&31))&1u;
      bool p1 = (sbm[d.y>>5]>>(d.y&31))&1u;
      bool p2 = (sbm[d.z>>5]>>(d.z&31))&1u;
      bool p3 = (sbm[d.w>>5]>>(d.w&31))&1u;
      if (__ballot_sync(0xffffffffu, p0|p1|p2|p3)){
        int e0 = 4*i;
        int s0=0,s1=0,s2=0,s3=0;
        if (p0) s0 = srcp[e0];
        if (p1) s1 = srcp[e0+1];
        if (p2) s2 = srcp[e0+2];
        if (p3) s3 = srcp[e0+3];
        wappend2(p0, make_int2(s0,d.x), &g_cnt1, g_list1, CAP1);
        wappend2(p1, make_int2(s1,d.y), &g_cnt1, g_list1, CAP1);
        wappend2(p2, make_int2(s2,d.z), &g_cnt1, g_list1, CAP1);
        wappend2(p3, make_int2(s3,d.w), &g_cnt1, g_list1, CAP1);
        if (p0) grow(s0, g_nl2, &g_n2, 1, 0);
        if (p1) grow(s1, g_nl2, &g_n2, 1, 0);
        if (p2) grow(s2, g_nl2, &g_n2, 1, 0);
        if (p3) grow(s3, g_nl2, &g_n2, 1, 0);
      }
    }
  }
  gbar();

  // ---- P3: scan2 (refreshed snapshot of S2) + grow S3 ----
  {
    uint4* s4 = (uint4*)sbm;
    const uint4* bm4 = (const uint4*)g_bmG;
    __syncthreads();
    for (int i = t; i < NWORDS/4; i += NTHR) s4[i] = bm4[i];
    __syncthreads();
    for (int i = gtid; i < EV; i += NT){
      int4 d = dst4[i];
      bool p0 = (sbm[d.x>>5]>>(d.x&31))&1u;
      bool p1 = (sbm[d.y>>5]>>(d.y&31))&1u;
      bool p2 = (sbm[d.z>>5]>>(d.z&31))&1u;
      bool p3 = (sbm[d.w>>5]>>(d.w&31))&1u;
      if (__ballot_sync(0xffffffffu, p0|p1|p2|p3)){
        int e0 = 4*i;
        int s0=0,s1=0,s2=0,s3=0;
        if (p0) s0 = srcp[e0];
        if (p1) s1 = srcp[e0+1];
        if (p2) s2 = srcp[e0+2];
        if (p3) s3 = srcp[e0+3];
        wappend2(p0, make_int2(s0,d.x), &g_cnt2, g_list2, CAP2);
        wappend2(p1, make_int2(s1,d.y), &g_cnt2, g_list2, CAP2);
        wappend2(p2, make_int2(s2,d.z), &g_cnt2, g_list2, CAP2);
        wappend2(p3, make_int2(s3,d.w), &g_cnt2, g_list2, CAP2);
        if (p0) grow(s0, g_nl3, &g_n3, 0, 0);
        if (p1) grow(s1, g_nl3, &g_n3, 0, 0);
        if (p2) grow(s2, g_nl3, &g_n3, 0, 0);
        if (p3) grow(s3, g_nl3, &g_n3, 0, 0);
      }
    }
  }
  gbar();

  // ---- P4: sparse h1 over nl1 ++ nl2 ++ nl3 : hs = rsqrt(deg)*(x@W1) ----
  {
    int n1 = g_n1, n2 = g_n2, n3 = g_n3;
    int ntot = n1 + n2 + n3;
    int sub  = t & 7;
    int slot = gtid >> 3;
    const int nslots = NT >> 3;
    int iters = (ntot + nslots - 1)/nslots;
    for (int it = 0; it < iters; it++){
      int i = slot + it*nslots;
      bool act = i < ntot;
      int node = 0;
      if (act) node = (i < n1) ? g_nl1[i] : (i < n1+n2) ? g_nl2[i-n1] : g_nl3[i-n1-n2];
      const float* xr = x + (size_t)node*128 + sub*4;
      float acc[8];
      #pragma unroll
      for (int j=0;j<8;j++) acc[j] = 0.f;
      #pragma unroll
      for (int q=0;q<4;q++){
        float4 xv = *(const float4*)(xr + 32*q);
        int kb = 32*q + 4*sub;
        #pragma unroll
        for (int j=0;j<8;j++){
          float4 wv = *(const float4*)&sWT[j*132 + kb];
          acc[j] += xv.x*wv.x + xv.y*wv.y + xv.z*wv.z + xv.w*wv.w;
        }
      }
      #pragma unroll
      for (int off=4; off; off>>=1){
        #pragma unroll
        for (int j=0;j<8;j++) acc[j] += __shfl_xor_sync(0xffffffffu, acc[j], off);
      }
      if (act && sub == 0){
        float r = rsqrtf(g_deg[node]);
        float* hp = g_hs + (size_t)node*8;
        *(float4*)hp     = make_float4(acc[0]*r,acc[1]*r,acc[2]*r,acc[3]*r);
        *(float4*)(hp+4) = make_float4(acc[4]*r,acc[5]*r,acc[6]*r,acc[7]*r);
      }
    }
  }
  gbar();

  // ---- P5: agg1 over list2 ----
  {
    int n = min(g_cnt2, CAP2);
    for (int i = gtid; i < n; i += NT){
      int2 sd = g_list2[i];
      const float* hp = g_hs + (size_t)sd.x*8;
      float4 a = *(const float4*)hp, b = *(const float4*)(hp+4);
      float* ap = g_acc1 + (size_t)sd.y*8;
      atomicAdd((float4*)ap, a);
      atomicAdd((float4*)(ap+4), b);
    }
  }
  gbar();

  // ---- P6: h2 over nl1 ++ nl2 ----
  {
    int n1 = g_n1, n2 = g_n2;
    int nS2 = n1 + n2;
    for (int i = gtid; i < nS2; i += NT){
      int node = (i < n1) ? g_nl1[i] : g_nl2[i - n1];
      float r = rsqrtf(g_deg[node]);
      const float* ap = g_acc1 + (size_t)node*8;
      const float* hp = g_hs  + (size_t)node*8;
      float x1[8];
      #pragma unroll
      for (int j=0;j<8;j++) x1[j] = fmaxf(r*(ap[j]+hp[j]) + sb1[j], 0.f);
      float* h2p = g_h2s + (size_t)node*8;
      #pragma unroll
      for (int j=0;j<8;j++){
        float s2 = 0.f;
        #pragma unroll
        for (int u=0;u<8;u++) s2 += x1[u]*sW2[u*8+j];
        h2p[j] = r*s2;
      }
    }
  }
  gbar();

  // ---- P7: agg2 over list1 ----
  {
    int n = min(g_cnt1, CAP1);
    for (int i = gtid; i < n; i += NT){
      int2 sd = g_list1[i];
      const float* hp = g_h2s + (size_t)sd.x*8;
      float4 a = *(const float4*)hp, b = *(const float4*)(hp+4);
      float* ap = g_acc2 + (size_t)sd.y*8;
      atomicAdd((float4*)ap, a);
      atomicAdd((float4*)(ap+4), b);
    }
  }
  gbar();

  // ---- P8: h3 over nl1 ----
  {
    int n1 = g_n1;
    for (int i = gtid; i < n1; i += NT){
      int node = g_nl1[i];
      float r = rsqrtf(g_deg[node]);
      const float* ap = g_acc2 + (size_t)node*8;
      const float* hp = g_h2s + (size_t)node*8;
      float s2 = 0.f;
      #pragma unroll
      for (int j=0;j<8;j++) s2 += fmaxf(r*(ap[j]+hp[j]) + sb2[j], 0.f)*sW3[j];
      g_h3s[node] = r*s2;
    }
  }
  gbar();

  // ---- P9: agg3 over list0 ----
  {
    int n = min(g_cnt0, CAP0);
    for (int i = gtid; i < n; i += NT){
      int2 sd = g_list0[i];
      atomicAdd(&g_acc3[sd.y], g_h3s[sd.x]);
    }
  }
  gbar();

  // ---- P10: head MLP at targets ----
  if (blockIdx.x == 0 && t < NB){
    int node = g_tn[t];
    float r = rsqrtf(g_deg[node]);
    float f[17];
    const float* a1 = g_acc1 + (size_t)node*8;
    const float* h1 = g_hs  + (size_t)node*8;
    const float* a2 = g_acc2 + (size_t)node*8;
    const float* h2 = g_h2s + (size_t)node*8;
    #pragma unroll
    for (int j=0;j<8;j++) f[j]   = fmaxf(r*(a1[j]+h1[j]) + sb1[j], 0.f);
    #pragma unroll
    for (int j=0;j<8;j++) f[8+j] = fmaxf(r*(a2[j]+h2[j]) + sb2[j], 0.f);
    f[16] = fmaxf(r*(g_acc3[node]+g_h3s[node]) + b3[0], 0.f);
    float z[16];
    #pragma unroll
    for (int j=0;j<16;j++){
      float s2 = sbl1[j];
      #pragma unroll
      for (int u=0;u<17;u++) s2 += f[u]*sWl1[u*16+j];
      z[j] = fmaxf(s2, 0.f);
    }
    #pragma unroll
    for (int o=0;o<2;o++){
      float s2 = sbl2[o];
      #pragma unroll
      for (int u=0;u<16;u++) s2 += z[u]*sWl2[u*2+o];
      out[t*2+o] = s2;
    }
  }
}

extern "C" void kernel_launch(void* const* d_in, const int* in_sizes, int n_in,
                              void* d_out, int out_size){
  const float* x    = (const float*)d_in[0];
  const int*   ei   = (const int*)  d_in[1];
  const int*   tgt  = (const int*)  d_in[2];
  const float* W1   = (const float*)d_in[3];
  const float* b1   = (const float*)d_in[4];
  const float* W2   = (const float*)d_in[5];
  const float* b2   = (const float*)d_in[6];
  const float* W3   = (const float*)d_in[7];
  const float* b3   = (const float*)d_in[8];
  const float* Wl1  = (const float*)d_in[9];
  const float* bl1  = (const float*)d_in[10];
  const float* Wl2  = (const float*)d_in[11];
  const float* bl2  = (const float*)d_in[12];
  const int* srcp = ei;
  const int4* dst4 = (const int4*)(ei + EE);
  float* out = (float*)d_out;

  cudaFuncSetAttribute(k_mega, cudaFuncAttributeMaxDynamicSharedMemorySize, NWORDS*4);
  k_mega<<<NBLK, NTHR, NWORDS*4>>>(x, srcp, dst4, tgt,
                                   W1, b1, W2, b2, W3, b3,
                                   Wl1, bl1, Wl2, bl2, out);
}